// round 1
// baseline (speedup 1.0000x reference)
#include <cuda_runtime.h>
#include <math.h>

#define N_NODES 100000
#define F_DIM   128
#define E_EDGES 600000
#define G_GRAPHS 1000
#define WIDTHC  4
#define KCH     3
#define HDIM    256
#define C2      (2*HDIM)

// ---------------- scratch (static device memory; no allocs) ----------------
__device__ float d_H1  [(size_t)N_NODES * F_DIM];          // 51.2 MB
__device__ float d_Tx  [(size_t)N_NODES * 3 * F_DIM];      // 153.6 MB  [Tx0|Tx1|Tx2] row stride 384
__device__ float d_Hfin[(size_t)N_NODES * 4 * F_DIM];      // 204.8 MB
__device__ float d_H3  [(size_t)N_NODES * HDIM];           // 102.4 MB
__device__ float d_H4  [(size_t)N_NODES * HDIM];           // 102.4 MB
__device__ float d_deg [N_NODES];
__device__ float d_dis [N_NODES];
__device__ float d_ew  [E_EDGES];
__device__ float d_scr [N_NODES];
__device__ float d_Wbig[3 * F_DIM * WIDTHC * F_DIM];       // 384 x 512
__device__ float d_bbig[WIDTHC * F_DIM];                   // 512
__device__ float d_T1  [G_GRAPHS * HDIM];
__device__ float d_T2  [G_GRAPHS * HDIM];
__device__ float d_X1  [G_GRAPHS * HDIM];
__device__ float d_X2  [G_GRAPHS * HDIM];
__device__ float d_hc  [G_GRAPHS * C2];
__device__ float d_mu  [C2];
__device__ float d_rstd[C2];

// ---------------- small utility kernels ----------------
__global__ void zero_kernel(float* p, size_t n) {
    size_t i = (size_t)blockIdx.x * blockDim.x + threadIdx.x;
    size_t stride = (size_t)gridDim.x * blockDim.x;
    for (; i < n; i += stride) p[i] = 0.f;
}

// Wbig[(kk*128+i)*512 + (w*128+j)] = cheb_W[w][kk][i][j];  bbig[w*128+j] = cheb_b[w][j]
__global__ void build_wbig(const float* __restrict__ chebW, const float* __restrict__ chebb,
                           float* __restrict__ Wbig, float* __restrict__ bbig) {
    int idx = blockIdx.x * 256 + threadIdx.x;
    if (idx < 3 * 128 * 512) {
        int row = idx / 512, col = idx % 512;
        int kk = row / 128, i = row % 128;
        int w = col / 128, j = col % 128;
        Wbig[idx] = chebW[(((w * 3) + kk) * 128 + i) * 128 + j];
    }
    if (idx < 512) {
        int w = idx / 128, j = idx % 128;
        bbig[idx] = chebb[w * 128 + j];
    }
}

__global__ void deg_kernel(const int* __restrict__ src, int e, float* __restrict__ deg) {
    int i = blockIdx.x * 256 + threadIdx.x;
    if (i < e) atomicAdd(&deg[src[i]], 1.0f);
}

__global__ void dis_kernel(const float* __restrict__ deg, float* __restrict__ dis, int n) {
    int i = blockIdx.x * 256 + threadIdx.x;
    if (i < n) {
        float d = deg[i];
        dis[i] = (d > 0.f) ? rsqrtf(fmaxf(d, 1.f)) : 0.f;
    }
}

__global__ void ew_kernel(const int* __restrict__ src, const int* __restrict__ dst,
                          const float* __restrict__ dis, float* __restrict__ ew, int e) {
    int i = blockIdx.x * 256 + threadIdx.x;
    if (i < e) ew[i] = -(dis[src[i]] * dis[dst[i]]);
}

// y[dst] += ew[e] * x[src]; x,y are column slices of d_Tx (row stride 384), 128 floats wide.
// one warp per edge; lane handles 4 consecutive floats (float4 load).
__global__ void prop_kernel(const float* __restrict__ x, const float* __restrict__ ew,
                            const int* __restrict__ src, const int* __restrict__ dst,
                            float* __restrict__ y, int e) {
    int warp = (blockIdx.x * 256 + threadIdx.x) >> 5;
    int lane = threadIdx.x & 31;
    if (warp >= e) return;
    int s = src[warp], d = dst[warp];
    float c = ew[warp];
    float4 v = *reinterpret_cast<const float4*>(&x[(size_t)s * 384 + lane * 4]);
    float* yr = &y[(size_t)d * 384 + lane * 4];
    atomicAdd(yr + 0, c * v.x);
    atomicAdd(yr + 1, c * v.y);
    atomicAdd(yr + 2, c * v.z);
    atomicAdd(yr + 3, c * v.w);
}

// Tx2 = 2*prop(Tx1) - Tx0   (prop result already in Tx2 slot)
__global__ void tx2_fix(float* __restrict__ Tx, int n) {
    int idx = blockIdx.x * 256 + threadIdx.x;
    if (idx >= n * 128) return;
    int v = idx >> 7, f = idx & 127;
    size_t base = (size_t)v * 384;
    Tx[base + 256 + f] = 2.f * Tx[base + 256 + f] - Tx[base + f];
}

// ---------------- fp32 SGEMM: C = act(A[MxK] @ B[KxN] + bias), leaky 0.01 ----------------
// 128x128 block tile, BK=8, 256 threads, 8x8 microtile. Requires N % 128 == 0, K % 8 == 0.
__global__ __launch_bounds__(256, 2)
void sgemm(const float* __restrict__ A, int lda,
           const float* __restrict__ B, int ldb,
           const float* __restrict__ bias,
           float* __restrict__ C, int ldc,
           int M, int N, int K, int act) {
    __shared__ float As[8][128];
    __shared__ float Bs[8][128];
    const int tid = threadIdx.x;
    const int bm = blockIdx.y * 128;
    const int bn = blockIdx.x * 128;
    const int arow = tid >> 1;
    const int acol = (tid & 1) * 4;
    const int brow = tid >> 5;
    const int bcol = (tid & 31) * 4;
    const int ty = tid >> 4;
    const int tx = tid & 15;

    float acc[8][8];
#pragma unroll
    for (int i = 0; i < 8; i++)
#pragma unroll
        for (int j = 0; j < 8; j++) acc[i][j] = 0.f;

    for (int k0 = 0; k0 < K; k0 += 8) {
        float4 av = make_float4(0.f, 0.f, 0.f, 0.f);
        if (bm + arow < M)
            av = *reinterpret_cast<const float4*>(&A[(size_t)(bm + arow) * lda + k0 + acol]);
        As[acol + 0][arow] = av.x;
        As[acol + 1][arow] = av.y;
        As[acol + 2][arow] = av.z;
        As[acol + 3][arow] = av.w;
        *reinterpret_cast<float4*>(&Bs[brow][bcol]) =
            *reinterpret_cast<const float4*>(&B[(size_t)(k0 + brow) * ldb + bn + bcol]);
        __syncthreads();
#pragma unroll
        for (int k = 0; k < 8; k++) {
            float a[8], b[8];
            *reinterpret_cast<float4*>(&a[0]) = *reinterpret_cast<const float4*>(&As[k][ty * 8]);
            *reinterpret_cast<float4*>(&a[4]) = *reinterpret_cast<const float4*>(&As[k][ty * 8 + 4]);
            *reinterpret_cast<float4*>(&b[0]) = *reinterpret_cast<const float4*>(&Bs[k][tx * 8]);
            *reinterpret_cast<float4*>(&b[4]) = *reinterpret_cast<const float4*>(&Bs[k][tx * 8 + 4]);
#pragma unroll
            for (int i = 0; i < 8; i++)
#pragma unroll
                for (int j = 0; j < 8; j++)
                    acc[i][j] += a[i] * b[j];
        }
        __syncthreads();
    }
#pragma unroll
    for (int i = 0; i < 8; i++) {
        int r = bm + ty * 8 + i;
        if (r >= M) continue;
#pragma unroll
        for (int j = 0; j < 8; j++) {
            int c = bn + tx * 8 + j;
            float v = acc[i][j] + bias[c];
            if (act) v = (v > 0.f) ? v : 0.01f * v;
            C[(size_t)r * ldc + c] = v;
        }
    }
}

// ---------------- pooling / BN / classifier ----------------
__global__ void scores_kernel(const float* __restrict__ H4, const float* __restrict__ T2,
                              const int* __restrict__ gid, float* __restrict__ scores, int n) {
    int warp = (blockIdx.x * 256 + threadIdx.x) >> 5;
    int lane = threadIdx.x & 31;
    if (warp >= n) return;
    int g = gid[warp];
    const float* hv = &H4[(size_t)warp * HDIM];
    const float* tv = &T2[(size_t)g * HDIM];
    float s = 0.f;
#pragma unroll
    for (int i = 0; i < HDIM / 32; i++)
        s += hv[lane + 32 * i] * tv[lane + 32 * i];
#pragma unroll
    for (int o = 16; o > 0; o >>= 1) s += __shfl_xor_sync(0xffffffffu, s, o);
    if (lane == 0) scores[warp] = s;
}

// hc[g] = [ sum_{v in graph g} H4[v]*scores[v]/npg  |  X2[g] ]
// graph_id is repeat(arange(G), npg) -> contiguous node ranges.
__global__ void assemble_kernel(const float* __restrict__ H4, const float* __restrict__ scores,
                                const float* __restrict__ X2, float* __restrict__ hc, int npg) {
    int g = blockIdx.x;
    int tid = threadIdx.x;  // 512 threads
    if (tid < HDIM) {
        float s = 0.f;
        int base = g * npg;
        for (int i = 0; i < npg; i++) {
            int v = base + i;
            s += H4[(size_t)v * HDIM + tid] * scores[v];
        }
        hc[g * C2 + tid] = s / (float)npg;
    } else {
        hc[g * C2 + tid] = X2[g * HDIM + (tid - HDIM)];
    }
}

__global__ void bn_stats(const float* __restrict__ hc, float* __restrict__ mu,
                         float* __restrict__ rstd, int g) {
    int c = blockIdx.x;  // 0..511
    int tid = threadIdx.x;
    __shared__ float red[256];
    float s = 0.f;
    for (int i = tid; i < g; i += 256) s += hc[i * C2 + c];
    red[tid] = s;
    __syncthreads();
    for (int o = 128; o > 0; o >>= 1) {
        if (tid < o) red[tid] += red[tid + o];
        __syncthreads();
    }
    float m = red[0] / (float)g;
    __syncthreads();
    float sq = 0.f;
    for (int i = tid; i < g; i += 256) {
        float d = hc[i * C2 + c] - m;
        sq += d * d;
    }
    red[tid] = sq;
    __syncthreads();
    for (int o = 128; o > 0; o >>= 1) {
        if (tid < o) red[tid] += red[tid + o];
        __syncthreads();
    }
    if (tid == 0) {
        mu[c] = m;
        rstd[c] = rsqrtf(red[0] / (float)g + 1e-5f);
    }
}

__global__ void bn_final(const float* __restrict__ hc, const float* __restrict__ mu,
                         const float* __restrict__ rstd, const float* __restrict__ gamma,
                         const float* __restrict__ beta, const float* __restrict__ W7,
                         const float* __restrict__ b7, float* __restrict__ out) {
    int g = blockIdx.x;
    int tid = threadIdx.x;  // 256
    __shared__ float r0[256], r1[256];
    float s0 = 0.f, s1 = 0.f;
    for (int c = tid; c < C2; c += 256) {
        float v = (hc[g * C2 + c] - mu[c]) * rstd[c] * gamma[c] + beta[c];
        s0 += v * W7[c * 2 + 0];
        s1 += v * W7[c * 2 + 1];
    }
    r0[tid] = s0; r1[tid] = s1;
    __syncthreads();
    for (int o = 128; o > 0; o >>= 1) {
        if (tid < o) { r0[tid] += r0[tid + o]; r1[tid] += r1[tid + o]; }
        __syncthreads();
    }
    if (tid == 0) {
        out[g * 2 + 0] = r0[0] + b7[0];
        out[g * 2 + 1] = r1[0] + b7[1];
    }
}

// ---------------- launch ----------------
extern "C" void kernel_launch(void* const* d_in, const int* in_sizes, int n_in,
                              void* d_out, int out_size) {
    const float* features = (const float*)d_in[0];
    const int*   edge     = (const int*)d_in[1];
    const int*   gid      = (const int*)d_in[2];
    const float* xLx      = (const float*)d_in[3];
    const float* W1 = (const float*)d_in[4];  const float* b1 = (const float*)d_in[5];
    const float* W2 = (const float*)d_in[6];  const float* b2 = (const float*)d_in[7];
    const float* chebW = (const float*)d_in[8]; const float* chebb = (const float*)d_in[9];
    const float* W3 = (const float*)d_in[10]; const float* b3 = (const float*)d_in[11];
    const float* W4 = (const float*)d_in[12]; const float* b4 = (const float*)d_in[13];
    const float* W5 = (const float*)d_in[14]; const float* b5 = (const float*)d_in[15];
    const float* W6 = (const float*)d_in[16]; const float* b6 = (const float*)d_in[17];
    const float* W8 = (const float*)d_in[18]; const float* b8 = (const float*)d_in[19];
    const float* W9 = (const float*)d_in[20]; const float* b9 = (const float*)d_in[21];
    const float* W7 = (const float*)d_in[22]; const float* b7 = (const float*)d_in[23];
    const float* gamma = (const float*)d_in[24]; const float* beta = (const float*)d_in[25];
    float* out = (float*)d_out;

    int n = in_sizes[0] / F_DIM;   // 100000
    int e = in_sizes[1] / 2;       // 600000
    int g = in_sizes[3] / F_DIM;   // 1000
    int npg = n / g;               // 100

    float *H1, *Tx, *Hfin, *H3, *H4, *deg, *dis, *ew, *scr, *Wbig, *bbig;
    float *T1, *T2, *X1, *X2, *hc, *mu, *rstd;
    cudaGetSymbolAddress((void**)&H1, d_H1);
    cudaGetSymbolAddress((void**)&Tx, d_Tx);
    cudaGetSymbolAddress((void**)&Hfin, d_Hfin);
    cudaGetSymbolAddress((void**)&H3, d_H3);
    cudaGetSymbolAddress((void**)&H4, d_H4);
    cudaGetSymbolAddress((void**)&deg, d_deg);
    cudaGetSymbolAddress((void**)&dis, d_dis);
    cudaGetSymbolAddress((void**)&ew, d_ew);
    cudaGetSymbolAddress((void**)&scr, d_scr);
    cudaGetSymbolAddress((void**)&Wbig, d_Wbig);
    cudaGetSymbolAddress((void**)&bbig, d_bbig);
    cudaGetSymbolAddress((void**)&T1, d_T1);
    cudaGetSymbolAddress((void**)&T2, d_T2);
    cudaGetSymbolAddress((void**)&X1, d_X1);
    cudaGetSymbolAddress((void**)&X2, d_X2);
    cudaGetSymbolAddress((void**)&hc, d_hc);
    cudaGetSymbolAddress((void**)&mu, d_mu);
    cudaGetSymbolAddress((void**)&rstd, d_rstd);

    const int* src = edge;
    const int* dst = edge + e;

    // zero atomic-target scratch
    zero_kernel<<<2048, 256>>>(Tx, (size_t)n * 384);
    zero_kernel<<<256, 256>>>(deg, (size_t)n);

    // repack ChebConv weights
    build_wbig<<<(3 * 128 * 512 + 255) / 256, 256>>>(chebW, chebb, Wbig, bbig);

    // edge weights: -D^-1/2 A D^-1/2
    deg_kernel<<<(e + 255) / 256, 256>>>(src, e, deg);
    dis_kernel<<<(n + 255) / 256, 256>>>(deg, dis, n);
    ew_kernel<<<(e + 255) / 256, 256>>>(src, dst, dis, ew, e);

    int mblocks = (n + 127) / 128;
    int gblocks = (g + 127) / 128;

    // node MLP
    sgemm<<<dim3(1, mblocks), 256>>>(features, 128, W1, 128, b1, H1, 128, n, 128, 128, 1);
    sgemm<<<dim3(1, mblocks), 256>>>(H1, 128, W2, 128, b2, Tx, 384, n, 128, 128, 1);  // Tx0

    // Chebyshev recursion (shared across widths)
    prop_kernel<<<(e * 32 + 255) / 256, 256>>>(Tx, ew, src, dst, Tx + 128, e);        // Tx1 = prop(Tx0)
    prop_kernel<<<(e * 32 + 255) / 256, 256>>>(Tx + 128, ew, src, dst, Tx + 256, e);  // raw prop(Tx1)
    tx2_fix<<<(n * 128 + 255) / 256, 256>>>(Tx, n);                                   // Tx2 = 2*prop(Tx1)-Tx0

    // fused cheb GEMM: [Tx0|Tx1|Tx2] @ Wbig + bbig  (no act)
    sgemm<<<dim3(4, mblocks), 256>>>(Tx, 384, Wbig, 512, bbig, Hfin, 512, n, 512, 384, 0);
    sgemm<<<dim3(2, mblocks), 256>>>(Hfin, 512, W3, 256, b3, H3, 256, n, 256, 512, 1);
    sgemm<<<dim3(2, mblocks), 256>>>(H3, 256, W4, 256, b4, H4, 256, n, 256, 256, 1);

    // graph-side MLPs
    sgemm<<<dim3(2, gblocks), 256>>>(xLx, 128, W8, 256, b8, T1, 256, g, 256, 128, 1);
    sgemm<<<dim3(2, gblocks), 256>>>(T1, 256, W9, 256, b9, T2, 256, g, 256, 256, 1);
    sgemm<<<dim3(2, gblocks), 256>>>(xLx, 128, W5, 256, b5, X1, 256, g, 256, 128, 0);
    sgemm<<<dim3(2, gblocks), 256>>>(X1, 256, W6, 256, b6, X2, 256, g, 256, 256, 1);

    // attention pooling + concat
    scores_kernel<<<(n + 7) / 8, 256>>>(H4, T2, gid, scr, n);
    assemble_kernel<<<g, 512>>>(H4, scr, X2, hc, npg);

    // BatchNorm + classifier
    bn_stats<<<C2, 256>>>(hc, mu, rstd, g);
    bn_final<<<g, 256>>>(hc, mu, rstd, gamma, beta, W7, b7, out);
}

// round 3
// speedup vs baseline: 1.9655x; 1.9655x over previous
#include <cuda_runtime.h>
#include <cuda_bf16.h>
#include <cstdint>
#include <math.h>

#define N_NODES 100000
#define F_DIM   128
#define E_EDGES 600000
#define G_GRAPHS 1000
#define HDIM    256
#define C2      (2*HDIM)

// ---------------- scratch (static device memory; no allocs) ----------------
__device__ float d_H1  [(size_t)N_NODES * F_DIM];
__device__ float d_Tx  [(size_t)N_NODES * 3 * F_DIM];      // [Tx0|Tx1|Tx2] row stride 384
__device__ float d_Hfin[(size_t)N_NODES * 4 * F_DIM];
__device__ float d_H3  [(size_t)N_NODES * HDIM];
__device__ float d_H4  [(size_t)N_NODES * HDIM];
__device__ float d_deg [N_NODES];
__device__ float d_dis [N_NODES];
__device__ float d_ew  [E_EDGES];
__device__ float d_scr [N_NODES];
__device__ float d_bbig[512];
__device__ float d_T1  [G_GRAPHS * HDIM];
__device__ float d_T2  [G_GRAPHS * HDIM];
__device__ float d_X1  [G_GRAPHS * HDIM];
__device__ float d_X2  [G_GRAPHS * HDIM];
__device__ float d_hc  [G_GRAPHS * C2];
__device__ float d_mu  [C2];
__device__ float d_rstd[C2];
// transposed weights [N,K] fp32
__device__ float d_W1t [128 * 128];
__device__ float d_W2t [128 * 128];
__device__ float d_Wbt [512 * 384];
__device__ float d_W3t [256 * 512];
__device__ float d_W4t [256 * 256];
__device__ float d_W5t [256 * 128];
__device__ float d_W6t [256 * 256];
__device__ float d_W8t [256 * 128];
__device__ float d_W9t [256 * 256];

// ---------------- bf16 split helpers ----------------
__device__ __forceinline__ uint32_t pack_hi(float a, float b) {
    __nv_bfloat162 h = __floats2bfloat162_rn(a, b);
    return *reinterpret_cast<uint32_t*>(&h);
}
__device__ __forceinline__ uint32_t pack_lo(float a, float b) {
    float ra = a - __bfloat162float(__float2bfloat16(a));
    float rb = b - __bfloat162float(__float2bfloat16(b));
    __nv_bfloat162 l = __floats2bfloat162_rn(ra, rb);
    return *reinterpret_cast<uint32_t*>(&l);
}

#define MMA_BF16(d, a, b)                                                      \
    asm volatile(                                                              \
        "mma.sync.aligned.m16n8k16.row.col.f32.bf16.bf16.f32 "                 \
        "{%0,%1,%2,%3}, {%4,%5,%6,%7}, {%8,%9}, {%0,%1,%2,%3};"                \
        : "+f"((d)[0]), "+f"((d)[1]), "+f"((d)[2]), "+f"((d)[3])               \
        : "r"((a).x), "r"((a).y), "r"((a).z), "r"((a).w),                      \
          "r"((b).x), "r"((b).y))

// ---------------- tensor-core GEMM: C[M,N] = act(A[M,K] @ Bt[N,K]^T + bias) ----
// 128x128 CTA tile, BK=32, 256 threads (8 warps, 2x4), warp tile 64x32.
// bf16x3 split (hi*hi + hi*lo + lo*hi) for ~1e-5 fp32 accuracy.
// SMEM holds fragment-permuted tiles: A 16x16 tile = 512B (lane*16 + word*4),
// B 16(k)x8(n) tile = 256B (lane*8 + word*4). Fragment load = LDS.128 / LDS.64.
__global__ __launch_bounds__(256)
void mma_gemm(const float* __restrict__ A, int lda,
              const float* __restrict__ Bt, int ldb,
              const float* __restrict__ bias,
              float* __restrict__ C, int ldc,
              int M, int K, int act) {
    __shared__ uint32_t sAhi[2048];   // 8 mtiles x 2 ktiles x 128 u32
    __shared__ uint32_t sAlo[2048];
    __shared__ uint32_t sBhi[2048];   // 16 ntiles x 2 ktiles x 64 u32
    __shared__ uint32_t sBlo[2048];

    const int tid = threadIdx.x;
    const int lane = tid & 31, wid = tid >> 5;
    const int wm = wid >> 2, wn = wid & 3;          // 2 x 4 warps
    const int bm = blockIdx.y * 128, bn = blockIdx.x * 128;

    float acc[4][4][4];
#pragma unroll
    for (int i = 0; i < 4; i++)
#pragma unroll
        for (int j = 0; j < 4; j++)
#pragma unroll
            for (int r = 0; r < 4; r++) acc[i][j][r] = 0.f;

    for (int kc = 0; kc < K; kc += 32) {
        // ---- A tile: 128 rows x 32 k fp32 -> hi/lo bf16, fragment-permuted ----
#pragma unroll
        for (int q = 0; q < 4; q++) {
            int idx = tid + q * 256;
            int row = idx >> 3, c0 = (idx & 7) * 4;
            float4 v = make_float4(0.f, 0.f, 0.f, 0.f);
            if (bm + row < M)
                v = *reinterpret_cast<const float4*>(&A[(size_t)(bm + row) * lda + kc + c0]);
            int mt = row >> 4, rr = row & 15, kt = c0 >> 4, cc = c0 & 15;
            int g = rr & 7;
            int base = (mt * 2 + kt) * 128;
            int l1 = g * 4 + ((cc & 7) >> 1);
            int l2 = g * 4 + (((cc + 2) & 7) >> 1);
            int w  = (rr >> 3) + ((cc >> 3) << 1);
            sAhi[base + l1 * 4 + w] = pack_hi(v.x, v.y);
            sAhi[base + l2 * 4 + w] = pack_hi(v.z, v.w);
            sAlo[base + l1 * 4 + w] = pack_lo(v.x, v.y);
            sAlo[base + l2 * 4 + w] = pack_lo(v.z, v.w);
        }
        // ---- B tile: 128 n-rows x 32 k (Bt is [N,K] row-major == mma col layout) ----
#pragma unroll
        for (int q = 0; q < 4; q++) {
            int idx = tid + q * 256;
            int n = idx >> 3, c0 = (idx & 7) * 4;
            float4 v = *reinterpret_cast<const float4*>(&Bt[(size_t)(bn + n) * ldb + kc + c0]);
            int nt = n >> 3, g = n & 7, kt = c0 >> 4, kk = c0 & 15;
            int base = (nt * 2 + kt) * 64;
            int l1 = g * 4 + ((kk & 7) >> 1);
            int l2 = g * 4 + (((kk + 2) & 7) >> 1);
            int w  = kk >> 3;
            sBhi[base + l1 * 2 + w] = pack_hi(v.x, v.y);
            sBhi[base + l2 * 2 + w] = pack_hi(v.z, v.w);
            sBlo[base + l1 * 2 + w] = pack_lo(v.x, v.y);
            sBlo[base + l2 * 2 + w] = pack_lo(v.z, v.w);
        }
        __syncthreads();

#pragma unroll
        for (int kt = 0; kt < 2; kt++) {
            uint4 ah[4], al[4];
            uint2 bh[4], bl[4];
#pragma unroll
            for (int i = 0; i < 4; i++) {
                int mt = wm * 4 + i;
                ah[i] = *reinterpret_cast<uint4*>(&sAhi[(mt * 2 + kt) * 128 + lane * 4]);
                al[i] = *reinterpret_cast<uint4*>(&sAlo[(mt * 2 + kt) * 128 + lane * 4]);
            }
#pragma unroll
            for (int j = 0; j < 4; j++) {
                int nt = wn * 4 + j;
                bh[j] = *reinterpret_cast<uint2*>(&sBhi[(nt * 2 + kt) * 64 + lane * 2]);
                bl[j] = *reinterpret_cast<uint2*>(&sBlo[(nt * 2 + kt) * 64 + lane * 2]);
            }
#pragma unroll
            for (int i = 0; i < 4; i++)
#pragma unroll
                for (int j = 0; j < 4; j++) {
                    MMA_BF16(acc[i][j], ah[i], bh[j]);
                    MMA_BF16(acc[i][j], ah[i], bl[j]);
                    MMA_BF16(acc[i][j], al[i], bh[j]);
                }
        }
        __syncthreads();
    }

    // ---- epilogue: c0,c1 row g; c2,c3 row g+8 ----
    const int g = lane >> 2, tg = lane & 3;
#pragma unroll
    for (int i = 0; i < 4; i++) {
        int row0 = bm + wm * 64 + i * 16 + g;
#pragma unroll
        for (int j = 0; j < 4; j++) {
            int col = bn + wn * 32 + j * 8 + tg * 2;
            float b0 = bias[col], b1 = bias[col + 1];
            if (row0 < M) {
                float2 v;
                v.x = acc[i][j][0] + b0;
                v.y = acc[i][j][1] + b1;
                if (act) {
                    v.x = v.x > 0.f ? v.x : 0.01f * v.x;
                    v.y = v.y > 0.f ? v.y : 0.01f * v.y;
                }
                *reinterpret_cast<float2*>(&C[(size_t)row0 * ldc + col]) = v;
            }
            if (row0 + 8 < M) {
                float2 v;
                v.x = acc[i][j][2] + b0;
                v.y = acc[i][j][3] + b1;
                if (act) {
                    v.x = v.x > 0.f ? v.x : 0.01f * v.x;
                    v.y = v.y > 0.f ? v.y : 0.01f * v.y;
                }
                *reinterpret_cast<float2*>(&C[(size_t)(row0 + 8) * ldc + col]) = v;
            }
        }
    }
}

// ---------------- small utility kernels ----------------
__global__ void zero_kernel(float* p, size_t n) {
    size_t i = (size_t)blockIdx.x * blockDim.x + threadIdx.x;
    size_t stride = (size_t)gridDim.x * blockDim.x;
    for (; i < n; i += stride) p[i] = 0.f;
}

__global__ void transpose_w(const float* __restrict__ W, float* __restrict__ Wt, int K, int N) {
    int idx = blockIdx.x * 256 + threadIdx.x;
    if (idx < K * N) {
        int k = idx / N, n = idx % N;
        Wt[n * K + k] = W[idx];
    }
}

// Wbt[n*384 + kk*128 + i] = chebW[w][kk][i][j], n = w*128+j ; bbig[w*128+j] = chebb[w][j]
__global__ void build_wbig_t(const float* __restrict__ chebW, const float* __restrict__ chebb,
                             float* __restrict__ Wbt, float* __restrict__ bbig) {
    int idx = blockIdx.x * 256 + threadIdx.x;
    if (idx < 512 * 384) {
        int n = idx / 384, k = idx % 384;
        int w = n / 128, j = n % 128;
        int kk = k / 128, i = k % 128;
        Wbt[idx] = chebW[(((w * 3) + kk) * 128 + i) * 128 + j];
    }
    if (idx < 512) {
        int w = idx / 128, j = idx % 128;
        bbig[idx] = chebb[w * 128 + j];
    }
}

__global__ void deg_kernel(const int* __restrict__ src, int e, float* __restrict__ deg) {
    int i = blockIdx.x * 256 + threadIdx.x;
    if (i < e) atomicAdd(&deg[src[i]], 1.0f);
}

__global__ void dis_kernel(const float* __restrict__ deg, float* __restrict__ dis, int n) {
    int i = blockIdx.x * 256 + threadIdx.x;
    if (i < n) {
        float d = deg[i];
        dis[i] = (d > 0.f) ? rsqrtf(fmaxf(d, 1.f)) : 0.f;
    }
}

__global__ void ew_kernel(const int* __restrict__ src, const int* __restrict__ dst,
                          const float* __restrict__ dis, float* __restrict__ ew, int e) {
    int i = blockIdx.x * 256 + threadIdx.x;
    if (i < e) ew[i] = -(dis[src[i]] * dis[dst[i]]);
}

// y[dst] += ew[e] * x[src]; rows stride 384, 128 floats wide; warp per edge.
__global__ void prop_kernel(const float* __restrict__ x, const float* __restrict__ ew,
                            const int* __restrict__ src, const int* __restrict__ dst,
                            float* __restrict__ y, int e) {
    int warp = (blockIdx.x * 256 + threadIdx.x) >> 5;
    int lane = threadIdx.x & 31;
    if (warp >= e) return;
    int s = src[warp], d = dst[warp];
    float c = ew[warp];
    float4 v = *reinterpret_cast<const float4*>(&x[(size_t)s * 384 + lane * 4]);
    float* yr = &y[(size_t)d * 384 + lane * 4];
    atomicAdd(yr + 0, c * v.x);
    atomicAdd(yr + 1, c * v.y);
    atomicAdd(yr + 2, c * v.z);
    atomicAdd(yr + 3, c * v.w);
}

__global__ void tx2_fix(float* __restrict__ Tx, int n) {
    int idx = blockIdx.x * 256 + threadIdx.x;
    if (idx >= n * 128) return;
    int v = idx >> 7, f = idx & 127;
    size_t base = (size_t)v * 384;
    Tx[base + 256 + f] = 2.f * Tx[base + 256 + f] - Tx[base + f];
}

// ---------------- pooling / BN / classifier ----------------
__global__ void scores_kernel(const float* __restrict__ H4, const float* __restrict__ T2,
                              const int* __restrict__ gid, float* __restrict__ scores, int n) {
    int warp = (blockIdx.x * 256 + threadIdx.x) >> 5;
    int lane = threadIdx.x & 31;
    if (warp >= n) return;
    int g = gid[warp];
    const float* hv = &H4[(size_t)warp * HDIM];
    const float* tv = &T2[(size_t)g * HDIM];
    float s = 0.f;
#pragma unroll
    for (int i = 0; i < HDIM / 32; i++)
        s += hv[lane + 32 * i] * tv[lane + 32 * i];
#pragma unroll
    for (int o = 16; o > 0; o >>= 1) s += __shfl_xor_sync(0xffffffffu, s, o);
    if (lane == 0) scores[warp] = s;
}

__global__ void assemble_kernel(const float* __restrict__ H4, const float* __restrict__ scores,
                                const float* __restrict__ X2, float* __restrict__ hc, int npg) {
    int g = blockIdx.x;
    int tid = threadIdx.x;  // 512
    if (tid < HDIM) {
        float s = 0.f;
        int base = g * npg;
        for (int i = 0; i < npg; i++) {
            int v = base + i;
            s += H4[(size_t)v * HDIM + tid] * scores[v];
        }
        hc[g * C2 + tid] = s / (float)npg;
    } else {
        hc[g * C2 + tid] = X2[g * HDIM + (tid - HDIM)];
    }
}

__global__ void bn_stats(const float* __restrict__ hc, float* __restrict__ mu,
                         float* __restrict__ rstd, int g) {
    int c = blockIdx.x;
    int tid = threadIdx.x;
    __shared__ float red[256];
    float s = 0.f;
    for (int i = tid; i < g; i += 256) s += hc[i * C2 + c];
    red[tid] = s;
    __syncthreads();
    for (int o = 128; o > 0; o >>= 1) {
        if (tid < o) red[tid] += red[tid + o];
        __syncthreads();
    }
    float m = red[0] / (float)g;
    __syncthreads();
    float sq = 0.f;
    for (int i = tid; i < g; i += 256) {
        float d = hc[i * C2 + c] - m;
        sq += d * d;
    }
    red[tid] = sq;
    __syncthreads();
    for (int o = 128; o > 0; o >>= 1) {
        if (tid < o) red[tid] += red[tid + o];
        __syncthreads();
    }
    if (tid == 0) {
        mu[c] = m;
        rstd[c] = rsqrtf(red[0] / (float)g + 1e-5f);
    }
}

__global__ void bn_final(const float* __restrict__ hc, const float* __restrict__ mu,
                         const float* __restrict__ rstd, const float* __restrict__ gamma,
                         const float* __restrict__ beta, const float* __restrict__ W7,
                         const float* __restrict__ b7, float* __restrict__ out) {
    int g = blockIdx.x;
    int tid = threadIdx.x;
    __shared__ float r0[256], r1[256];
    float s0 = 0.f, s1 = 0.f;
    for (int c = tid; c < C2; c += 256) {
        float v = (hc[g * C2 + c] - mu[c]) * rstd[c] * gamma[c] + beta[c];
        s0 += v * W7[c * 2 + 0];
        s1 += v * W7[c * 2 + 1];
    }
    r0[tid] = s0; r1[tid] = s1;
    __syncthreads();
    for (int o = 128; o > 0; o >>= 1) {
        if (tid < o) { r0[tid] += r0[tid + o]; r1[tid] += r1[tid + o]; }
        __syncthreads();
    }
    if (tid == 0) {
        out[g * 2 + 0] = r0[0] + b7[0];
        out[g * 2 + 1] = r1[0] + b7[1];
    }
}

// ---------------- launch ----------------
static void launch_tc(const float* A, int lda, const float* Bt, int ldb, const float* bias,
                      float* C, int ldc, int M, int N, int K, int act) {
    dim3 grid(N / 128, (M + 127) / 128);
    mma_gemm<<<grid, 256>>>(A, lda, Bt, ldb, bias, C, ldc, M, K, act);
}

extern "C" void kernel_launch(void* const* d_in, const int* in_sizes, int n_in,
                              void* d_out, int out_size) {
    const float* features = (const float*)d_in[0];
    const int*   edge     = (const int*)d_in[1];
    const int*   gid      = (const int*)d_in[2];
    const float* xLx      = (const float*)d_in[3];
    const float* W1 = (const float*)d_in[4];  const float* b1 = (const float*)d_in[5];
    const float* W2 = (const float*)d_in[6];  const float* b2 = (const float*)d_in[7];
    const float* chebW = (const float*)d_in[8]; const float* chebb = (const float*)d_in[9];
    const float* W3 = (const float*)d_in[10]; const float* b3 = (const float*)d_in[11];
    const float* W4 = (const float*)d_in[12]; const float* b4 = (const float*)d_in[13];
    const float* W5 = (const float*)d_in[14]; const float* b5 = (const float*)d_in[15];
    const float* W6 = (const float*)d_in[16]; const float* b6 = (const float*)d_in[17];
    const float* W8 = (const float*)d_in[18]; const float* b8 = (const float*)d_in[19];
    const float* W9 = (const float*)d_in[20]; const float* b9 = (const float*)d_in[21];
    const float* W7 = (const float*)d_in[22]; const float* b7 = (const float*)d_in[23];
    const float* gamma = (const float*)d_in[24]; const float* beta = (const float*)d_in[25];
    float* out = (float*)d_out;

    int n = in_sizes[0] / F_DIM;   // 100000
    int e = in_sizes[1] / 2;       // 600000
    int g = in_sizes[3] / F_DIM;   // 1000
    int npg = n / g;

    float *H1, *Tx, *Hfin, *H3, *H4, *deg, *dis, *ew, *scr, *bbig;
    float *T1, *T2, *X1, *X2, *hc, *mu, *rstd;
    float *W1t, *W2t, *Wbt, *W3t, *W4t, *W5t, *W6t, *W8t, *W9t;
    cudaGetSymbolAddress((void**)&H1, d_H1);
    cudaGetSymbolAddress((void**)&Tx, d_Tx);
    cudaGetSymbolAddress((void**)&Hfin, d_Hfin);
    cudaGetSymbolAddress((void**)&H3, d_H3);
    cudaGetSymbolAddress((void**)&H4, d_H4);
    cudaGetSymbolAddress((void**)&deg, d_deg);
    cudaGetSymbolAddress((void**)&dis, d_dis);
    cudaGetSymbolAddress((void**)&ew, d_ew);
    cudaGetSymbolAddress((void**)&scr, d_scr);
    cudaGetSymbolAddress((void**)&bbig, d_bbig);
    cudaGetSymbolAddress((void**)&T1, d_T1);
    cudaGetSymbolAddress((void**)&T2, d_T2);
    cudaGetSymbolAddress((void**)&X1, d_X1);
    cudaGetSymbolAddress((void**)&X2, d_X2);
    cudaGetSymbolAddress((void**)&hc, d_hc);
    cudaGetSymbolAddress((void**)&mu, d_mu);
    cudaGetSymbolAddress((void**)&rstd, d_rstd);
    cudaGetSymbolAddress((void**)&W1t, d_W1t);
    cudaGetSymbolAddress((void**)&W2t, d_W2t);
    cudaGetSymbolAddress((void**)&Wbt, d_Wbt);
    cudaGetSymbolAddress((void**)&W3t, d_W3t);
    cudaGetSymbolAddress((void**)&W4t, d_W4t);
    cudaGetSymbolAddress((void**)&W5t, d_W5t);
    cudaGetSymbolAddress((void**)&W6t, d_W6t);
    cudaGetSymbolAddress((void**)&W8t, d_W8t);
    cudaGetSymbolAddress((void**)&W9t, d_W9t);

    const int* src = edge;
    const int* dst = edge + e;

    // zero atomic-target scratch
    zero_kernel<<<2048, 256>>>(Tx, (size_t)n * 384);
    zero_kernel<<<256, 256>>>(deg, (size_t)n);

    // weight prep (transpose to [N,K])
    transpose_w<<<(128 * 128 + 255) / 256, 256>>>(W1, W1t, 128, 128);
    transpose_w<<<(128 * 128 + 255) / 256, 256>>>(W2, W2t, 128, 128);
    build_wbig_t<<<(512 * 384 + 255) / 256, 256>>>(chebW, chebb, Wbt, bbig);
    transpose_w<<<(512 * 256 + 255) / 256, 256>>>(W3, W3t, 512, 256);
    transpose_w<<<(256 * 256 + 255) / 256, 256>>>(W4, W4t, 256, 256);
    transpose_w<<<(128 * 256 + 255) / 256, 256>>>(W5, W5t, 128, 256);
    transpose_w<<<(256 * 256 + 255) / 256, 256>>>(W6, W6t, 256, 256);
    transpose_w<<<(128 * 256 + 255) / 256, 256>>>(W8, W8t, 128, 256);
    transpose_w<<<(256 * 256 + 255) / 256, 256>>>(W9, W9t, 256, 256);

    // edge weights: -D^-1/2 A D^-1/2
    deg_kernel<<<(e + 255) / 256, 256>>>(src, e, deg);
    dis_kernel<<<(n + 255) / 256, 256>>>(deg, dis, n);
    ew_kernel<<<(e + 255) / 256, 256>>>(src, dst, dis, ew, e);

    // node MLP
    launch_tc(features, 128, W1t, 128, b1, H1, 128, n, 128, 128, 1);
    launch_tc(H1, 128, W2t, 128, b2, Tx, 384, n, 128, 128, 1);  // Tx0

    // Chebyshev recursion (shared across widths)
    prop_kernel<<<(e * 32 + 255) / 256, 256>>>(Tx, ew, src, dst, Tx + 128, e);
    prop_kernel<<<(e * 32 + 255) / 256, 256>>>(Tx + 128, ew, src, dst, Tx + 256, e);
    tx2_fix<<<(n * 128 + 255) / 256, 256>>>(Tx, n);

    // fused cheb GEMM + node head
    launch_tc(Tx, 384, Wbt, 384, bbig, Hfin, 512, n, 512, 384, 0);
    launch_tc(Hfin, 512, W3t, 512, b3, H3, 256, n, 256, 512, 1);
    launch_tc(H3, 256, W4t, 256, b4, H4, 256, n, 256, 256, 1);

    // graph-side MLPs
    launch_tc(xLx, 128, W8t, 128, b8, T1, 256, g, 256, 128, 1);
    launch_tc(T1, 256, W9t, 256, b9, T2, 256, g, 256, 256, 1);
    launch_tc(xLx, 128, W5t, 128, b5, X1, 256, g, 256, 128, 0);
    launch_tc(X1, 256, W6t, 256, b6, X2, 256, g, 256, 256, 1);

    // attention pooling + concat
    scores_kernel<<<(n + 7) / 8, 256>>>(H4, T2, gid, scr, n);
    assemble_kernel<<<g, 512>>>(H4, scr, X2, hc, npg);

    // BatchNorm + classifier
    bn_stats<<<C2, 256>>>(hc, mu, rstd, g);
    bn_final<<<g, 256>>>(hc, mu, rstd, gamma, beta, W7, b7, out);
}